// round 8
// baseline (speedup 1.0000x reference)
#include <cuda_runtime.h>

// Problem constants (fixed by the reference): B=4, S=2048, E=16, H=4, D_K=4
#define BB 4
#define SS 2048
#define EE 16
#define HH 4
#define DK 4
#define NBH (BB*HH)

#define KSPLIT 16
#define KT (SS/KSPLIT)       // 128 keys per split tile
#define THREADS 128
#define QPT 4
#define QBLK (THREADS*QPT)   // 512 queries per CTA

typedef unsigned long long u64;

// Scratch (allocation-free rule: __device__ globals)
// Layout: parta[b][sq][h][ks] as float4 rows; partl[b][sq][h][ks] scalar.
// (split innermost -> epi loads are CTA-linear; attn stores scatter, hidden)
__device__ float g_parta[BB * SS * HH * KSPLIT * 4];
__device__ float g_partl[BB * SS * HH * KSPLIT];

__device__ __forceinline__ float ex2f(float x) {
    float y; asm("ex2.approx.ftz.f32 %0, %1;" : "=f"(y) : "f"(x)); return y;
}
__device__ __forceinline__ u64 pk2(float lo, float hi) {
    u64 r; asm("mov.b64 %0, {%1, %2};" : "=l"(r) : "f"(lo), "f"(hi)); return r;
}
__device__ __forceinline__ void upk2(u64 v, float& lo, float& hi) {
    asm("mov.b64 {%0, %1}, %2;" : "=f"(lo), "=f"(hi) : "l"(v));
}
__device__ __forceinline__ u64 fma2(u64 a, u64 b, u64 c) {
    u64 d; asm("fma.rn.f32x2 %0, %1, %2, %3;" : "=l"(d) : "l"(a), "l"(b), "l"(c)); return d;
}
__device__ __forceinline__ u64 mul2(u64 a, u64 b) {
    u64 d; asm("mul.rn.f32x2 %0, %1, %2;" : "=l"(d) : "l"(a), "l"(b)); return d;
}
__device__ __forceinline__ u64 add2(u64 a, u64 b) {
    u64 d; asm("add.rn.f32x2 %0, %1, %2;" : "=l"(d) : "l"(a), "l"(b)); return d;
}

// ---------------------------------------------------------------------------
// Fused kernel: per-CTA K/V projection of its key tile + attention partials.
// K/V key-pair packed: u64 = (val[key 2j], val[key 2j+1]) per dim.
// QPT=4 queries/thread for ILP across the ex2 dependency chain.
// Bounded scores (|s_log2| < ~12) -> no max subtraction.
// ---------------------------------------------------------------------------
__global__ void __launch_bounds__(THREADS)
attn_kernel(const float* __restrict__ x,
            const float* __restrict__ theta,
            const float* __restrict__ Wk,
            const float* __restrict__ Wv) {
    __shared__ ulonglong2 Ka[KT/2];      // (d0 pair, d1 pair) per key-pair
    __shared__ ulonglong2 Kb[KT/2];      // (d2 pair, d3 pair)
    __shared__ ulonglong2 Va[KT/2];
    __shared__ ulonglong2 Vb[KT/2];
    __shared__ float wk[DK * EE];
    __shared__ float wv[DK * EE];

    int tid = threadIdx.x;               // 0..127
    int qb  = blockIdx.x;                // 0..3
    int bh  = blockIdx.y;                // 0..15
    int ks  = blockIdx.z;                // 0..15
    int b = bh >> 2, h = bh & 3;

    if (tid < DK * EE) {
        wk[tid] = Wk[h * DK * EE + tid];
        wv[tid] = Wv[h * DK * EE + tid];
    }

    // ---- queries: q = cos(x+theta) * (0.5*log2 e), duplicated-packed ----
    const float4 thv = *reinterpret_cast<const float4*>(theta + h * DK);
    const float SCL = 0.72134752044448170368f;   // 0.5 * log2(e)
    u64 qd0[QPT], qd1[QPT], qd2[QPT], qd3[QPT];
    int sq0 = qb * QBLK + tid;
    #pragma unroll
    for (int qi = 0; qi < QPT; qi++) {
        int sq = sq0 + qi * THREADS;
        const float4 xq = *reinterpret_cast<const float4*>(
            x + (b * SS + sq) * EE + h * DK);
        float c0 = __cosf(xq.x + thv.x) * SCL;
        float c1 = __cosf(xq.y + thv.y) * SCL;
        float c2 = __cosf(xq.z + thv.z) * SCL;
        float c3 = __cosf(xq.w + thv.w) * SCL;
        qd0[qi] = pk2(c0, c0); qd1[qi] = pk2(c1, c1);
        qd2[qi] = pk2(c2, c2); qd3[qi] = pk2(c3, c3);
    }
    __syncthreads();

    // ---- K/V tile build: thread t<64 computes key tokens (2t, 2t+1) ----
    if (tid < KT/2) {
        float kk[2][DK], vv[2][DK];
        #pragma unroll
        for (int t = 0; t < 2; t++) {
            int tok = 2 * tid + t;
            const float4* x4 = reinterpret_cast<const float4*>(
                x + ((b * SS + ks * KT) + tok) * EE);
            float xr[EE];
            #pragma unroll
            for (int r = 0; r < 4; r++) {
                float4 q = x4[r];
                xr[4*r+0] = q.x; xr[4*r+1] = q.y; xr[4*r+2] = q.z; xr[4*r+3] = q.w;
            }
            #pragma unroll
            for (int d = 0; d < DK; d++) {
                float a = 0.f, c = 0.f;
                #pragma unroll
                for (int e = 0; e < EE; e++) {
                    a = fmaf(xr[e], wk[d * EE + e], a);
                    c = fmaf(xr[e], wv[d * EE + e], c);
                }
                kk[t][d] = a; vv[t][d] = c;
            }
        }
        ulonglong2 t0, t1;
        t0.x = pk2(kk[0][0], kk[1][0]); t0.y = pk2(kk[0][1], kk[1][1]);
        t1.x = pk2(kk[0][2], kk[1][2]); t1.y = pk2(kk[0][3], kk[1][3]);
        Ka[tid] = t0; Kb[tid] = t1;
        t0.x = pk2(vv[0][0], vv[1][0]); t0.y = pk2(vv[0][1], vv[1][1]);
        t1.x = pk2(vv[0][2], vv[1][2]); t1.y = pk2(vv[0][3], vv[1][3]);
        Va[tid] = t0; Vb[tid] = t1;
    }
    __syncthreads();

    u64 A0[QPT], A1[QPT], A2[QPT], A3[QPT], L[QPT];
    #pragma unroll
    for (int qi = 0; qi < QPT; qi++) {
        A0[qi] = 0ULL; A1[qi] = 0ULL; A2[qi] = 0ULL; A3[qi] = 0ULL; L[qi] = 0ULL;
    }

    #pragma unroll 4
    for (int jp = 0; jp < KT/2; jp++) {
        ulonglong2 ka = Ka[jp];              // broadcast LDS.128
        ulonglong2 kb = Kb[jp];
        ulonglong2 va = Va[jp];
        ulonglong2 vb = Vb[jp];
        #pragma unroll
        for (int qi = 0; qi < QPT; qi++) {
            u64 s = mul2(qd0[qi], ka.x);
            s = fma2(qd1[qi], ka.y, s);
            s = fma2(qd2[qi], kb.x, s);
            s = fma2(qd3[qi], kb.y, s);       // (score_even, score_odd)
            float se, so; upk2(s, se, so);
            u64 pp = pk2(ex2f(se), ex2f(so));
            L[qi]  = add2(L[qi], pp);
            A0[qi] = fma2(pp, va.x, A0[qi]);
            A1[qi] = fma2(pp, va.y, A1[qi]);
            A2[qi] = fma2(pp, vb.x, A2[qi]);
            A3[qi] = fma2(pp, vb.y, A3[qi]);
        }
    }

    // partial stores: [b][sq][h][ks] (scattered, hidden behind compute)
    #pragma unroll
    for (int qi = 0; qi < QPT; qi++) {
        int sq = sq0 + qi * THREADS;
        int idx = ((b * SS + sq) * HH + h) * KSPLIT + ks;
        float e0, o0, e1, o1, e2, o2, e3, o3, le, lo;
        upk2(A0[qi], e0, o0); upk2(A1[qi], e1, o1);
        upk2(A2[qi], e2, o2); upk2(A3[qi], e3, o3);
        upk2(L[qi], le, lo);
        reinterpret_cast<float4*>(g_parta)[idx] =
            make_float4(e0 + o0, e1 + o1, e2 + o2, e3 + o3);
        g_partl[idx] = le + lo;
    }
}

// ---------------------------------------------------------------------------
// Epilogue: thread = (token-head, split). With layout [b][sq][h][ks], the
// float4 load index is exactly blockIdx.x*256 + tid -> fully coalesced.
// Butterfly shuffle-reduce over 16 splits, normalize, then 16 threads/CTA
// do out = att @ Wc^T with transposed Wc in smem.
// ---------------------------------------------------------------------------
#define EPI_THREADS 256      // 16 token-heads (= 4 tokens) per CTA

__global__ void __launch_bounds__(EPI_THREADS)
epi_kernel(const float* __restrict__ Wc, float* __restrict__ out) {
    __shared__ float wct[EE * EE];            // wct[e*16+o] = Wc[o*16+e]
    __shared__ float att[4][EE + 1];

    int tid = threadIdx.x;                    // 0..255
    wct[(tid & 15) * EE + (tid >> 4)] = Wc[tid];

    int s        = tid & 15;                  // split (lane-minor)
    int th_local = tid >> 4;                  // token-head 0..15 (h fastest)

    // linear, fully-coalesced loads
    int gidx = blockIdx.x * EPI_THREADS + tid;
    float4 a = reinterpret_cast<const float4*>(g_parta)[gidx];
    float  l = g_partl[gidx];

    #pragma unroll
    for (int m = 1; m <= 8; m <<= 1) {
        a.x += __shfl_xor_sync(0xffffffffu, a.x, m);
        a.y += __shfl_xor_sync(0xffffffffu, a.y, m);
        a.z += __shfl_xor_sync(0xffffffffu, a.z, m);
        a.w += __shfl_xor_sync(0xffffffffu, a.w, m);
        l   += __shfl_xor_sync(0xffffffffu, l,   m);
    }

    if (s == 0) {
        float inv = 1.0f / l;
        int tl = th_local >> 2;               // local token 0..3
        int h  = th_local & 3;
        float* arow = att[tl] + h * DK;
        arow[0] = a.x * inv; arow[1] = a.y * inv;
        arow[2] = a.z * inv; arow[3] = a.w * inv;
    }
    __syncthreads();

    if (tid < 16) {
        int tl = tid >> 2, q = tid & 3;
        const float* ar = att[tl];
        float r[4] = {0.f, 0.f, 0.f, 0.f};
        #pragma unroll
        for (int e = 0; e < EE; e++) {
            float av = ar[e];
            #pragma unroll
            for (int d = 0; d < 4; d++)
                r[d] = fmaf(av, wct[e * EE + q * 4 + d], r[d]);
        }
        int tok = blockIdx.x * 4 + tl;
        reinterpret_cast<float4*>(out + tok * EE)[q] =
            make_float4(r[0], r[1], r[2], r[3]);
    }
}

// ---------------------------------------------------------------------------
extern "C" void kernel_launch(void* const* d_in, const int* in_sizes, int n_in,
                              void* d_out, int out_size) {
    const float* x     = (const float*)d_in[0];
    const float* theta = (const float*)d_in[1];
    const float* Wk    = (const float*)d_in[2];
    const float* Wv    = (const float*)d_in[3];
    const float* Wc    = (const float*)d_in[4];
    float* out = (float*)d_out;

    attn_kernel<<<dim3(SS / QBLK, NBH, KSPLIT), THREADS>>>(x, theta, Wk, Wv);
    epi_kernel<<<(BB * SS) / 4, EPI_THREADS>>>(Wc, out);
}

// round 9
// speedup vs baseline: 1.0009x; 1.0009x over previous
#include <cuda_runtime.h>

// Problem constants (fixed by the reference): B=4, S=2048, E=16, H=4, D_K=4
#define BB 4
#define SS 2048
#define EE 16
#define HH 4
#define DK 4
#define NBH (BB*HH)

#define KSPLIT 16
#define KT (SS/KSPLIT)       // 128 keys per split tile
#define THREADS 64
#define QPT 4
#define QBLK (THREADS*QPT)   // 256 queries per CTA

typedef unsigned long long u64;

// Scratch (allocation-free rule: __device__ globals)
// Layout: parta[b][sq][h][ks] as float4 rows; partl[b][sq][h][ks] scalar.
__device__ float g_parta[BB * SS * HH * KSPLIT * 4];
__device__ float g_partl[BB * SS * HH * KSPLIT];

__device__ __forceinline__ float ex2f(float x) {
    float y; asm("ex2.approx.ftz.f32 %0, %1;" : "=f"(y) : "f"(x)); return y;
}
__device__ __forceinline__ u64 pk2(float lo, float hi) {
    u64 r; asm("mov.b64 %0, {%1, %2};" : "=l"(r) : "f"(lo), "f"(hi)); return r;
}
__device__ __forceinline__ void upk2(u64 v, float& lo, float& hi) {
    asm("mov.b64 {%0, %1}, %2;" : "=f"(lo), "=f"(hi) : "l"(v));
}
__device__ __forceinline__ u64 fma2(u64 a, u64 b, u64 c) {
    u64 d; asm("fma.rn.f32x2 %0, %1, %2, %3;" : "=l"(d) : "l"(a), "l"(b), "l"(c)); return d;
}
__device__ __forceinline__ u64 mul2(u64 a, u64 b) {
    u64 d; asm("mul.rn.f32x2 %0, %1, %2;" : "=l"(d) : "l"(a), "l"(b)); return d;
}
__device__ __forceinline__ u64 add2(u64 a, u64 b) {
    u64 d; asm("add.rn.f32x2 %0, %1, %2;" : "=l"(d) : "l"(a), "l"(b)); return d;
}

// ---------------------------------------------------------------------------
// Fused kernel: per-CTA K/V projection of its key tile + attention partials.
// K/V key-pair packed: u64 = (val[key 2j], val[key 2j+1]) per dim.
// QPT=4 queries/thread for ILP across the ex2 dependency chain.
// Bounded scores (|s_log2| < ~12) -> no max subtraction.
// ---------------------------------------------------------------------------
__global__ void __launch_bounds__(THREADS)
attn_kernel(const float* __restrict__ x,
            const float* __restrict__ theta,
            const float* __restrict__ Wk,
            const float* __restrict__ Wv) {
    __shared__ ulonglong2 Ka[KT/2];      // (d0 pair, d1 pair) per key-pair
    __shared__ ulonglong2 Kb[KT/2];      // (d2 pair, d3 pair)
    __shared__ ulonglong2 Va[KT/2];
    __shared__ ulonglong2 Vb[KT/2];
    __shared__ float wk[DK * EE];
    __shared__ float wv[DK * EE];

    int tid = threadIdx.x;               // 0..63
    int qb  = blockIdx.x;                // 0..7
    int bh  = blockIdx.y;                // 0..15
    int ks  = blockIdx.z;                // 0..15
    int b = bh >> 2, h = bh & 3;

    // all 64 threads load the 64 weights of each matrix slice
    wk[tid] = Wk[h * DK * EE + tid];
    wv[tid] = Wv[h * DK * EE + tid];

    // ---- queries: q = cos(x+theta) * (0.5*log2 e), duplicated-packed ----
    const float4 thv = *reinterpret_cast<const float4*>(theta + h * DK);
    const float SCL = 0.72134752044448170368f;   // 0.5 * log2(e)
    u64 qd0[QPT], qd1[QPT], qd2[QPT], qd3[QPT];
    int sq0 = qb * QBLK + tid;
    #pragma unroll
    for (int qi = 0; qi < QPT; qi++) {
        int sq = sq0 + qi * THREADS;
        const float4 xq = *reinterpret_cast<const float4*>(
            x + (b * SS + sq) * EE + h * DK);
        float c0 = __cosf(xq.x + thv.x) * SCL;
        float c1 = __cosf(xq.y + thv.y) * SCL;
        float c2 = __cosf(xq.z + thv.z) * SCL;
        float c3 = __cosf(xq.w + thv.w) * SCL;
        qd0[qi] = pk2(c0, c0); qd1[qi] = pk2(c1, c1);
        qd2[qi] = pk2(c2, c2); qd3[qi] = pk2(c3, c3);
    }
    __syncthreads();

    // ---- K/V tile build: thread t computes key tokens (2t, 2t+1) ----
    {
        float kk[2][DK], vv[2][DK];
        #pragma unroll
        for (int t = 0; t < 2; t++) {
            int tok = 2 * tid + t;
            const float4* x4 = reinterpret_cast<const float4*>(
                x + ((b * SS + ks * KT) + tok) * EE);
            float xr[EE];
            #pragma unroll
            for (int r = 0; r < 4; r++) {
                float4 q = x4[r];
                xr[4*r+0] = q.x; xr[4*r+1] = q.y; xr[4*r+2] = q.z; xr[4*r+3] = q.w;
            }
            #pragma unroll
            for (int d = 0; d < DK; d++) {
                float a = 0.f, c = 0.f;
                #pragma unroll
                for (int e = 0; e < EE; e++) {
                    a = fmaf(xr[e], wk[d * EE + e], a);
                    c = fmaf(xr[e], wv[d * EE + e], c);
                }
                kk[t][d] = a; vv[t][d] = c;
            }
        }
        ulonglong2 t0, t1;
        t0.x = pk2(kk[0][0], kk[1][0]); t0.y = pk2(kk[0][1], kk[1][1]);
        t1.x = pk2(kk[0][2], kk[1][2]); t1.y = pk2(kk[0][3], kk[1][3]);
        Ka[tid] = t0; Kb[tid] = t1;
        t0.x = pk2(vv[0][0], vv[1][0]); t0.y = pk2(vv[0][1], vv[1][1]);
        t1.x = pk2(vv[0][2], vv[1][2]); t1.y = pk2(vv[0][3], vv[1][3]);
        Va[tid] = t0; Vb[tid] = t1;
    }
    __syncthreads();

    u64 A0[QPT], A1[QPT], A2[QPT], A3[QPT], L[QPT];
    #pragma unroll
    for (int qi = 0; qi < QPT; qi++) {
        A0[qi] = 0ULL; A1[qi] = 0ULL; A2[qi] = 0ULL; A3[qi] = 0ULL; L[qi] = 0ULL;
    }

    #pragma unroll 4
    for (int jp = 0; jp < KT/2; jp++) {
        ulonglong2 ka = Ka[jp];              // broadcast LDS.128
        ulonglong2 kb = Kb[jp];
        ulonglong2 va = Va[jp];
        ulonglong2 vb = Vb[jp];
        #pragma unroll
        for (int qi = 0; qi < QPT; qi++) {
            u64 s = mul2(qd0[qi], ka.x);
            s = fma2(qd1[qi], ka.y, s);
            s = fma2(qd2[qi], kb.x, s);
            s = fma2(qd3[qi], kb.y, s);       // (score_even, score_odd)
            float se, so; upk2(s, se, so);
            u64 pp = pk2(ex2f(se), ex2f(so));
            L[qi]  = add2(L[qi], pp);
            A0[qi] = fma2(pp, va.x, A0[qi]);
            A1[qi] = fma2(pp, va.y, A1[qi]);
            A2[qi] = fma2(pp, vb.x, A2[qi]);
            A3[qi] = fma2(pp, vb.y, A3[qi]);
        }
    }

    // partial stores: [b][sq][h][ks] (scattered, hidden behind compute)
    #pragma unroll
    for (int qi = 0; qi < QPT; qi++) {
        int sq = sq0 + qi * THREADS;
        int idx = ((b * SS + sq) * HH + h) * KSPLIT + ks;
        float e0, o0, e1, o1, e2, o2, e3, o3, le, lo;
        upk2(A0[qi], e0, o0); upk2(A1[qi], e1, o1);
        upk2(A2[qi], e2, o2); upk2(A3[qi], e3, o3);
        upk2(L[qi], le, lo);
        reinterpret_cast<float4*>(g_parta)[idx] =
            make_float4(e0 + o0, e1 + o1, e2 + o2, e3 + o3);
        g_partl[idx] = le + lo;
    }
}

// ---------------------------------------------------------------------------
// Epilogue: CTA = 16 tokens (64 token-heads). Thread (th, sg) loads 4
// CONSECUTIVE split-partials (coalesced), adds locally, then 2 shuffle
// levels combine the 4 split-groups. Normalize, then 64 threads do
// out = att @ Wc^T with transposed Wc in smem.
// ---------------------------------------------------------------------------
#define EPI_THREADS 256      // 64 token-heads x 4 split-groups
#define EPI_TOK 16           // tokens per CTA

__global__ void __launch_bounds__(EPI_THREADS)
epi_kernel(const float* __restrict__ Wc, float* __restrict__ out) {
    __shared__ float wct[EE * EE];            // wct[e*16+o] = Wc[o*16+e]
    __shared__ float att[EPI_TOK][EE + 1];

    int tid = threadIdx.x;                    // 0..255
    wct[(tid & 15) * EE + (tid >> 4)] = Wc[tid];

    int sg = tid & 3;                         // split-group (4 splits each)
    int th = tid >> 2;                        // token-head 0..63 (h fastest)

    // 4 consecutive float4 + 4 consecutive float loads (coalesced sweeps)
    int fbase = blockIdx.x * (EPI_TOK * HH * KSPLIT) + th * KSPLIT + sg * 4;
    const float4* pa = reinterpret_cast<const float4*>(g_parta);
    float4 a0 = pa[fbase + 0], a1 = pa[fbase + 1];
    float4 a2 = pa[fbase + 2], a3 = pa[fbase + 3];
    float  l0 = g_partl[fbase + 0], l1 = g_partl[fbase + 1];
    float  l2 = g_partl[fbase + 2], l3 = g_partl[fbase + 3];

    float ax = (a0.x + a1.x) + (a2.x + a3.x);
    float ay = (a0.y + a1.y) + (a2.y + a3.y);
    float az = (a0.z + a1.z) + (a2.z + a3.z);
    float aw = (a0.w + a1.w) + (a2.w + a3.w);
    float l  = (l0 + l1) + (l2 + l3);

    #pragma unroll
    for (int m = 1; m <= 2; m <<= 1) {
        ax += __shfl_xor_sync(0xffffffffu, ax, m);
        ay += __shfl_xor_sync(0xffffffffu, ay, m);
        az += __shfl_xor_sync(0xffffffffu, az, m);
        aw += __shfl_xor_sync(0xffffffffu, aw, m);
        l  += __shfl_xor_sync(0xffffffffu, l,  m);
    }

    if (sg == 0) {
        float inv = 1.0f / l;
        int tl = th >> 2;                     // local token 0..15
        int h  = th & 3;
        float* arow = att[tl] + h * DK;
        arow[0] = ax * inv; arow[1] = ay * inv;
        arow[2] = az * inv; arow[3] = aw * inv;
    }
    __syncthreads();

    if (tid < 64) {
        int tl = tid >> 2, q = tid & 3;
        const float* ar = att[tl];
        float r[4] = {0.f, 0.f, 0.f, 0.f};
        #pragma unroll
        for (int e = 0; e < EE; e++) {
            float av = ar[e];
            #pragma unroll
            for (int d = 0; d < 4; d++)
                r[d] = fmaf(av, wct[e * EE + q * 4 + d], r[d]);
        }
        int tok = blockIdx.x * EPI_TOK + tl;
        reinterpret_cast<float4*>(out + tok * EE)[q] =
            make_float4(r[0], r[1], r[2], r[3]);
    }
}

// ---------------------------------------------------------------------------
extern "C" void kernel_launch(void* const* d_in, const int* in_sizes, int n_in,
                              void* d_out, int out_size) {
    const float* x     = (const float*)d_in[0];
    const float* theta = (const float*)d_in[1];
    const float* Wk    = (const float*)d_in[2];
    const float* Wv    = (const float*)d_in[3];
    const float* Wc    = (const float*)d_in[4];
    float* out = (float*)d_out;

    attn_kernel<<<dim3(SS / QBLK, NBH, KSPLIT), THREADS>>>(x, theta, Wk, Wv);
    epi_kernel<<<(BB * SS) / EPI_TOK, EPI_THREADS>>>(Wc, out);
}